// round 4
// baseline (speedup 1.0000x reference)
#include <cuda_runtime.h>

#define FULL_MASK 0xFFFFFFFFu
static constexpr int HID = 32;
static constexpr int TT = 1024;
static constexpr int CELLS_PER_WARP = 3;

// ---- packed f32x2 helpers (sm_103a; ptxas never auto-fuses these) ----
__device__ __forceinline__ unsigned long long pack2(float lo, float hi) {
    unsigned long long r;
    asm("mov.b64 %0, {%1, %2};" : "=l"(r) : "f"(lo), "f"(hi));
    return r;
}
__device__ __forceinline__ void unpack2(unsigned long long v, float& lo, float& hi) {
    asm("mov.b64 {%0, %1}, %2;" : "=f"(lo), "=f"(hi) : "l"(v));
}
__device__ __forceinline__ unsigned long long fma2(unsigned long long a,
                                                   unsigned long long b,
                                                   unsigned long long c) {
    unsigned long long d;
    asm("fma.rn.f32x2 %0, %1, %2, %3;" : "=l"(d) : "l"(a), "l"(b), "l"(c));
    return d;
}
__device__ __forceinline__ float ex2f(float x) {
    float r; asm("ex2.approx.f32 %0, %1;" : "=f"(r) : "f"(x)); return r;
}
__device__ __forceinline__ float rcpf(float x) {
    float r; asm("rcp.approx.f32 %0, %1;" : "=f"(r) : "f"(x)); return r;
}
// sigmoid(x) = 1 / (1 + 2^(-x*log2(e)))  — ex2/rcp approx are ~2^-22 rel err
__device__ __forceinline__ float fast_sigmoid(float x) {
    return rcpf(1.0f + ex2f(-1.4426950408889634f * x));
}
// tanh(x) = 2*sigmoid(2x) - 1
__device__ __forceinline__ float fast_tanh(float x) {
    float r = rcpf(1.0f + ex2f(-2.8853900817779268f * x));
    return fmaf(2.0f, r, -1.0f);
}

// One warp per CTA, THREE independent cells per warp sharing the
// register-resident W_hh (128 regs). 6 independent fma2 chains per step.
// Whole batch (4096 cells) fits in ONE resident wave:
// ceil(4096/3)=1366 warps over 148 SMs = 9.2 warps/SM < 10-warp reg limit.
__global__ void __launch_bounds__(32)
lstm_kernel(const float* __restrict__ x,
            const float* __restrict__ W_ih,
            const float* __restrict__ W_hh,
            const float* __restrict__ b_ih,
            const float* __restrict__ b_hh,
            const float* __restrict__ fc_W,
            const float* __restrict__ fc_b,
            float* __restrict__ out, int B)
{
    __shared__ __align__(16) float2 hbuf[CELLS_PER_WARP][2][HID];
    const int lane = threadIdx.x & 31;
    const int b0 = blockIdx.x * CELLS_PER_WARP;
    const int b1 = min(b0 + 1, B - 1);
    const int b2 = min(b0 + 2, B - 1);

    // Gate order (PyTorch): rows [0:32)=i, [32:64)=f, [64:96)=g, [96:128)=o
    unsigned long long Wif[HID], Wgo[HID];
    #pragma unroll
    for (int k = 0; k < HID; ++k) {
        Wif[k] = pack2(W_hh[(0 * HID + lane) * HID + k],
                       W_hh[(1 * HID + lane) * HID + k]);
        Wgo[k] = pack2(W_hh[(2 * HID + lane) * HID + k],
                       W_hh[(3 * HID + lane) * HID + k]);
    }
    const unsigned long long wih_if = pack2(W_ih[0 * HID + lane], W_ih[1 * HID + lane]);
    const unsigned long long wih_go = pack2(W_ih[2 * HID + lane], W_ih[3 * HID + lane]);
    const unsigned long long bias_if =
        pack2(b_ih[0 * HID + lane] + b_hh[0 * HID + lane],
              b_ih[1 * HID + lane] + b_hh[1 * HID + lane]);
    const unsigned long long bias_go =
        pack2(b_ih[2 * HID + lane] + b_hh[2 * HID + lane],
              b_ih[3 * HID + lane] + b_hh[3 * HID + lane]);

    float hA = 0.0f, cA = 0.0f;
    float hB = 0.0f, cB = 0.0f;
    float hC = 0.0f, cC = 0.0f;
    const float* xrowA = x + (size_t)b0 * TT;
    const float* xrowB = x + (size_t)b1 * TT;
    const float* xrowC = x + (size_t)b2 * TT;

    for (int t0 = 0; t0 < TT; t0 += 32) {
        // one coalesced 128B read per cell per 32 steps
        const float xbufA = xrowA[t0 + lane];
        const float xbufB = xrowB[t0 + lane];
        const float xbufC = xrowC[t0 + lane];
        for (int s = 0; s < 32; ++s) {
            const float xvA = __shfl_sync(FULL_MASK, xbufA, s);
            const float xvB = __shfl_sync(FULL_MASK, xbufB, s);
            const float xvC = __shfl_sync(FULL_MASK, xbufC, s);
            unsigned long long aif = fma2(pack2(xvA, xvA), wih_if, bias_if);
            unsigned long long ago = fma2(pack2(xvA, xvA), wih_go, bias_go);
            unsigned long long bif = fma2(pack2(xvB, xvB), wih_if, bias_if);
            unsigned long long bgo = fma2(pack2(xvB, xvB), wih_go, bias_go);
            unsigned long long cif = fma2(pack2(xvC, xvC), wih_if, bias_if);
            unsigned long long cgo = fma2(pack2(xvC, xvC), wih_go, bias_go);

            // broadcast all cells' h through ping-pong buffers, one sync
            float2* bufA = hbuf[0][s & 1];
            float2* bufB = hbuf[1][s & 1];
            float2* bufC = hbuf[2][s & 1];
            bufA[lane] = make_float2(hA, hA);
            bufB[lane] = make_float2(hB, hB);
            bufC[lane] = make_float2(hC, hC);
            __syncwarp();
            const ulonglong2* pA = reinterpret_cast<const ulonglong2*>(bufA);
            const ulonglong2* pB = reinterpret_cast<const ulonglong2*>(bufB);
            const ulonglong2* pC = reinterpret_cast<const ulonglong2*>(bufC);
            #pragma unroll
            for (int k2 = 0; k2 < HID / 2; ++k2) {
                const unsigned long long w0 = Wif[2 * k2];
                const unsigned long long w1 = Wgo[2 * k2];
                const unsigned long long w2 = Wif[2 * k2 + 1];
                const unsigned long long w3 = Wgo[2 * k2 + 1];
                const ulonglong2 ha = pA[k2];   // LDS.128 broadcast, N=1
                const ulonglong2 hb = pB[k2];
                const ulonglong2 hc = pC[k2];
                aif = fma2(w0, ha.x, aif);
                ago = fma2(w1, ha.x, ago);
                bif = fma2(w0, hb.x, bif);
                bgo = fma2(w1, hb.x, bgo);
                cif = fma2(w0, hc.x, cif);
                cgo = fma2(w1, hc.x, cgo);
                aif = fma2(w2, ha.y, aif);
                ago = fma2(w3, ha.y, ago);
                bif = fma2(w2, hb.y, bif);
                bgo = fma2(w3, hb.y, bgo);
                cif = fma2(w2, hc.y, cif);
                cgo = fma2(w3, hc.y, cgo);
            }

            float ai, af, ag, ao;
            unpack2(aif, ai, af);
            unpack2(ago, ag, ao);
            float bi, bf, bg, bo;
            unpack2(bif, bi, bf);
            unpack2(bgo, bg, bo);
            float ci, cf, cg, co;
            unpack2(cif, ci, cf);
            unpack2(cgo, cg, co);

            const float igA = fast_sigmoid(ai);
            const float fgA = fast_sigmoid(af);
            const float ggA = fast_tanh(ag);
            const float ogA = fast_sigmoid(ao);
            const float igB = fast_sigmoid(bi);
            const float fgB = fast_sigmoid(bf);
            const float ggB = fast_tanh(bg);
            const float ogB = fast_sigmoid(bo);
            const float igC = fast_sigmoid(ci);
            const float fgC = fast_sigmoid(cf);
            const float ggC = fast_tanh(cg);
            const float ogC = fast_sigmoid(co);

            cA = fmaf(fgA, cA, igA * ggA);
            cB = fmaf(fgB, cB, igB * ggB);
            cC = fmaf(fgC, cC, igC * ggC);
            hA = ogA * fast_tanh(cA);
            hB = ogB * fast_tanh(cB);
            hC = ogC * fast_tanh(cC);
        }
    }

    // out[b] = h . fc_W + fc_b  (warp reduce, all cells)
    const float w = fc_W[lane];
    float vA = hA * w;
    float vB = hB * w;
    float vC = hC * w;
    #pragma unroll
    for (int off = 16; off; off >>= 1) {
        vA += __shfl_xor_sync(FULL_MASK, vA, off);
        vB += __shfl_xor_sync(FULL_MASK, vB, off);
        vC += __shfl_xor_sync(FULL_MASK, vC, off);
    }
    if (lane == 0) {
        const float fcb = fc_b[0];
        out[b0] = vA + fcb;
        if (b1 > b0) out[b1] = vB + fcb;
        if (b2 > b1) out[b2] = vC + fcb;
    }
}

extern "C" void kernel_launch(void* const* d_in, const int* in_sizes, int n_in,
                              void* d_out, int out_size) {
    const float* x    = (const float*)d_in[0];
    const float* W_ih = (const float*)d_in[1];
    const float* W_hh = (const float*)d_in[2];
    const float* b_ih = (const float*)d_in[3];
    const float* b_hh = (const float*)d_in[4];
    const float* fc_W = (const float*)d_in[5];
    const float* fc_b = (const float*)d_in[6];
    float* out = (float*)d_out;

    const int B = in_sizes[0] / TT;           // x is B*T*1 elements
    const int ctas = (B + CELLS_PER_WARP - 1) / CELLS_PER_WARP;
    lstm_kernel<<<ctas, 32>>>(x, W_ih, W_hh, b_ih, b_hh, fc_W, fc_b, out, B);
}

// round 5
// speedup vs baseline: 2.1869x; 2.1869x over previous
#include <cuda_runtime.h>

#define FULL_MASK 0xFFFFFFFFu
static constexpr int HID = 32;
static constexpr int TT = 1024;
static constexpr int WARPS_PER_CTA = 4;

// ---- packed f32x2 helpers (sm_103a; ptxas never auto-fuses these) ----
__device__ __forceinline__ unsigned long long pack2(float lo, float hi) {
    unsigned long long r;
    asm("mov.b64 %0, {%1, %2};" : "=l"(r) : "f"(lo), "f"(hi));
    return r;
}
__device__ __forceinline__ void unpack2(unsigned long long v, float& lo, float& hi) {
    asm("mov.b64 {%0, %1}, %2;" : "=f"(lo), "=f"(hi) : "l"(v));
}
__device__ __forceinline__ unsigned long long fma2(unsigned long long a,
                                                   unsigned long long b,
                                                   unsigned long long c) {
    unsigned long long d;
    asm("fma.rn.f32x2 %0, %1, %2, %3;" : "=l"(d) : "l"(a), "l"(b), "l"(c));
    return d;
}
__device__ __forceinline__ float ex2f(float x) {
    float r; asm("ex2.approx.f32 %0, %1;" : "=f"(r) : "f"(x)); return r;
}
__device__ __forceinline__ float rcpf(float x) {
    float r; asm("rcp.approx.f32 %0, %1;" : "=f"(r) : "f"(x)); return r;
}
// sigmoid(x) = 1 / (1 + 2^(-x*log2(e)))  — ex2/rcp approx are ~2^-22 rel err
__device__ __forceinline__ float fast_sigmoid(float x) {
    return rcpf(1.0f + ex2f(-1.4426950408889634f * x));
}
// tanh(x) = 2*sigmoid(2x) - 1
__device__ __forceinline__ float fast_tanh(float x) {
    float r = rcpf(1.0f + ex2f(-2.8853900817779268f * x));
    return fmaf(2.0f, r, -1.0f);
}

// One warp per cell, lane j owns hidden unit j.
// Weights packed ALONG K: Wg[gate][k2] = (w[j][2k2], w[j][2k2+1]) as f32x2.
// h stored SCALAR in smem; LDS.64 broadcast of (h_{2k}, h_{2k+1}) is directly
// the fma2 multiplicand — no duplication, no pack MOVs. 4 independent
// 16-deep accumulator chains (i, f, g, o), horizontal add at the end.
__global__ void __launch_bounds__(WARPS_PER_CTA * 32, 3)
lstm_kernel(const float* __restrict__ x,
            const float* __restrict__ W_ih,
            const float* __restrict__ W_hh,
            const float* __restrict__ b_ih,
            const float* __restrict__ b_hh,
            const float* __restrict__ fc_W,
            const float* __restrict__ fc_b,
            float* __restrict__ out, int B)
{
    __shared__ __align__(8) float hbuf[WARPS_PER_CTA][2][HID];
    const int warp = threadIdx.x >> 5;
    const int lane = threadIdx.x & 31;
    const int b = blockIdx.x * WARPS_PER_CTA + warp;
    if (b >= B) return;   // whole warp exits together (b is per-warp)

    // Gate order (PyTorch): rows [0:32)=i, [32:64)=f, [64:96)=g, [96:128)=o
    // Wg[g][k2] = (W_hh[g*32+lane][2k2], W_hh[g*32+lane][2k2+1])
    unsigned long long Wg[4][HID / 2];
    #pragma unroll
    for (int g = 0; g < 4; ++g) {
        const float* wrow = W_hh + (g * HID + lane) * HID;
        #pragma unroll
        for (int k2 = 0; k2 < HID / 2; ++k2)
            Wg[g][k2] = pack2(wrow[2 * k2], wrow[2 * k2 + 1]);
    }
    const float wih_i = W_ih[0 * HID + lane];
    const float wih_f = W_ih[1 * HID + lane];
    const float wih_g = W_ih[2 * HID + lane];
    const float wih_o = W_ih[3 * HID + lane];
    const float bias_i = b_ih[0 * HID + lane] + b_hh[0 * HID + lane];
    const float bias_f = b_ih[1 * HID + lane] + b_hh[1 * HID + lane];
    const float bias_g = b_ih[2 * HID + lane] + b_hh[2 * HID + lane];
    const float bias_o = b_ih[3 * HID + lane] + b_hh[3 * HID + lane];
    const unsigned long long zero64 = pack2(0.0f, 0.0f);

    float h = 0.0f, c = 0.0f;
    const float* xrow = x + (size_t)b * TT;   // x is [B, T, 1]

    for (int t0 = 0; t0 < TT; t0 += 32) {
        // one coalesced 128B read per warp per 32 steps
        const float xbuf = xrow[t0 + lane];
        for (int s = 0; s < 32; ++s) {
            const float xv = __shfl_sync(FULL_MASK, xbuf, s);
            // scalar gate bases (off the recurrent critical path)
            const float base_i = fmaf(xv, wih_i, bias_i);
            const float base_f = fmaf(xv, wih_f, bias_f);
            const float base_g = fmaf(xv, wih_g, bias_g);
            const float base_o = fmaf(xv, wih_o, bias_o);

            // publish h (scalar), then read back packed k-pairs
            float* buf = hbuf[warp][s & 1];
            buf[lane] = h;
            __syncwarp();
            const unsigned long long* hp =
                reinterpret_cast<const unsigned long long*>(buf);

            unsigned long long ai = zero64, af = zero64;
            unsigned long long ag = zero64, ao = zero64;
            #pragma unroll
            for (int k2 = 0; k2 < HID / 2; ++k2) {
                const unsigned long long hk = hp[k2];   // LDS.64 broadcast, 1 wf
                ai = fma2(Wg[0][k2], hk, ai);
                af = fma2(Wg[1][k2], hk, af);
                ag = fma2(Wg[2][k2], hk, ag);
                ao = fma2(Wg[3][k2], hk, ao);
            }

            float lo, hi;
            unpack2(ai, lo, hi);  const float gi = (lo + hi) + base_i;
            unpack2(af, lo, hi);  const float gf = (lo + hi) + base_f;
            unpack2(ag, lo, hi);  const float gg = (lo + hi) + base_g;
            unpack2(ao, lo, hi);  const float go = (lo + hi) + base_o;

            const float ig = fast_sigmoid(gi);
            const float fg = fast_sigmoid(gf);
            const float cg = fast_tanh(gg);
            const float og = fast_sigmoid(go);
            c = fmaf(fg, c, ig * cg);
            h = og * fast_tanh(c);
        }
    }

    // out[b] = h . fc_W + fc_b  (warp reduce)
    float v = h * fc_W[lane];
    #pragma unroll
    for (int off = 16; off; off >>= 1)
        v += __shfl_xor_sync(FULL_MASK, v, off);
    if (lane == 0) out[b] = v + fc_b[0];
}

extern "C" void kernel_launch(void* const* d_in, const int* in_sizes, int n_in,
                              void* d_out, int out_size) {
    const float* x    = (const float*)d_in[0];
    const float* W_ih = (const float*)d_in[1];
    const float* W_hh = (const float*)d_in[2];
    const float* b_ih = (const float*)d_in[3];
    const float* b_hh = (const float*)d_in[4];
    const float* fc_W = (const float*)d_in[5];
    const float* fc_b = (const float*)d_in[6];
    float* out = (float*)d_out;

    const int B = in_sizes[0] / TT;           // x is B*T*1 elements
    const int ctas = (B + WARPS_PER_CTA - 1) / WARPS_PER_CTA;
    lstm_kernel<<<ctas, WARPS_PER_CTA * 32>>>(x, W_ih, W_hh, b_ih, b_hh,
                                              fc_W, fc_b, out, B);
}